// round 6
// baseline (speedup 1.0000x reference)
#include <cuda_runtime.h>
#include <cuda_fp16.h>
#include <cstdint>

// Problem sizes (fixed)
#define MDIM 2048
#define NDIM 4096
#define KDIM 4096
// Tiling
#define MT 128        // CTA tile M
#define NT 256        // CTA tile N
#define KC 64         // K-chunk (halves)
#define NCHUNK (KDIM / KC)   // 64
#define STAGES 3
#define THREADS 256
#define ROWB 144      // padded smem row stride in bytes (64 halves = 128B data + 16B pad)

// Scratch (allocation-free rule: __device__ globals)
__device__ __half g_xh[(size_t)MDIM * KDIM];  // 16 MB
__device__ __half g_wh[(size_t)NDIM * KDIM];  // 32 MB

// ---------------- helpers ----------------
__device__ __forceinline__ uint32_t smem_u32(const void* p) {
    uint32_t a;
    asm("{ .reg .u64 t; cvta.to.shared.u64 t, %1; cvt.u32.u64 %0, t; }" : "=r"(a) : "l"(p));
    return a;
}
__device__ __forceinline__ void cp_async16(uint32_t dst, const void* src) {
    asm volatile("cp.async.cg.shared.global [%0], [%1], 16;" :: "r"(dst), "l"(src));
}
__device__ __forceinline__ void cp_commit() { asm volatile("cp.async.commit_group;"); }
__device__ __forceinline__ void cp_wait1()  { asm volatile("cp.async.wait_group 1;" ::: "memory"); }

__device__ __forceinline__ uint32_t lds32(uint32_t addr) {
    uint32_t v;
    asm volatile("ld.shared.b32 %0, [%1];" : "=r"(v) : "r"(addr));
    return v;
}
__device__ __forceinline__ void mma16816(float* d, const uint32_t* a, const uint32_t* b) {
    asm volatile(
        "mma.sync.aligned.m16n8k16.row.col.f32.f16.f16.f32 "
        "{%0,%1,%2,%3}, {%4,%5,%6,%7}, {%8,%9}, {%0,%1,%2,%3};"
        : "+f"(d[0]), "+f"(d[1]), "+f"(d[2]), "+f"(d[3])
        : "r"(a[0]), "r"(a[1]), "r"(a[2]), "r"(a[3]), "r"(b[0]), "r"(b[1]));
}

// ---------------- SMEM layout ----------------
#define OFF_BIAS 0
#define OFF_A 1024
#define A_BYTES (MT * ROWB)                       // 18432
#define B_BYTES (NT * ROWB)                       // 36864
#define STAGE_BYTES (A_BYTES + B_BYTES)           // 55296
#define SMEM_TOTAL (OFF_A + STAGES * STAGE_BYTES) // 166912

// ---------------- conversion kernels ----------------
__global__ void conv_x_kernel(const float4* __restrict__ x) {
    int i = blockIdx.x * blockDim.x + threadIdx.x;  // MDIM*KDIM/4 threads
    float4 v = x[i];
    __half2 h0 = __floats2half2_rn(v.x, v.y);
    __half2 h1 = __floats2half2_rn(v.z, v.w);
    uint2 r;
    r.x = *reinterpret_cast<uint32_t*>(&h0);
    r.y = *reinterpret_cast<uint32_t*>(&h1);
    reinterpret_cast<uint2*>(g_xh)[i] = r;
}

// w_q arrives as int32 on the wire (harness promotes int8; wire types are
// float32/int32/bfloat16 only). Each thread converts 4 weights.
__global__ void conv_w_kernel(const int4* __restrict__ wq, const float* __restrict__ sw) {
    int i = blockIdx.x * blockDim.x + threadIdx.x;  // NDIM*KDIM/4 threads
    int4 w = wq[i];
    int idx4 = i << 2;
    int o = idx4 >> 12;          // w_q layout (o, g, k): o*4096 + g*128 + k
    int g = (idx4 >> 7) & 31;
    float s = __ldg(&sw[(g << 12) + o]);  // s_w layout (g, o)
    __half2 h0 = __floats2half2_rn((float)w.x * s, (float)w.y * s);
    __half2 h1 = __floats2half2_rn((float)w.z * s, (float)w.w * s);
    uint2 r;
    r.x = *reinterpret_cast<uint32_t*>(&h0);
    r.y = *reinterpret_cast<uint32_t*>(&h1);
    reinterpret_cast<uint2*>(g_wh)[i] = r;
}

// ---------------- GEMM ----------------
__device__ __forceinline__ void load_chunk(uint32_t stage_base,
                                           const __half* Ag, const __half* Bg,
                                           int k0, int tid) {
    const uint32_t aB = stage_base;
    const uint32_t bB = stage_base + A_BYTES;
    // A: 128 rows x 8 x 16B = 1024 units -> 4 per thread
#pragma unroll
    for (int i = 0; i < 4; ++i) {
        int u = tid + i * THREADS;
        int row = u >> 3, c = u & 7;
        cp_async16(aB + row * ROWB + c * 16, Ag + (size_t)row * KDIM + k0 + c * 8);
    }
    // B: 256 rows -> 2048 units -> 8 per thread
#pragma unroll
    for (int i = 0; i < 8; ++i) {
        int u = tid + i * THREADS;
        int row = u >> 3, c = u & 7;
        cp_async16(bB + row * ROWB + c * 16, Bg + (size_t)row * KDIM + k0 + c * 8);
    }
}

__global__ void __launch_bounds__(THREADS, 1)
gemm_kernel(const float* __restrict__ bias, float* __restrict__ out) {
    extern __shared__ __align__(128) char smem[];
    const uint32_t sb = smem_u32(smem);
    const int tid = threadIdx.x;
    const int wid = tid >> 5;
    const int lane = tid & 31;
    const int gid = lane >> 2;   // groupID (0..7)
    const int tig = lane & 3;    // thread-in-group

    // column-major over M so consecutive CTAs share the B tile in L2
    const int bm = blockIdx.x & 15;   // 16 m-tiles
    const int bn = blockIdx.x >> 4;   // 16 n-tiles
    const int m0 = bm * MT;
    const int n0 = bn * NT;

    // warp tile: 64x64.  wm in {0,1}, wn in {0..3}
    const int wm0 = (wid & 1) * 64;
    const int wn0 = (wid >> 1) * 64;

    ((float*)(smem + OFF_BIAS))[tid] = bias[n0 + tid];

    const __half* Ag = g_xh + (size_t)m0 * KDIM;
    const __half* Bg = g_wh + (size_t)n0 * KDIM;

    // prologue: stages 0,1 in flight
#pragma unroll
    for (int s = 0; s < STAGES - 1; ++s) {
        load_chunk(sb + OFF_A + s * STAGE_BYTES, Ag, Bg, s * KC, tid);
        cp_commit();
    }

    float acc[4][8][4];
#pragma unroll
    for (int g = 0; g < 4; ++g)
#pragma unroll
        for (int j = 0; j < 8; ++j)
#pragma unroll
            for (int e = 0; e < 4; ++e) acc[g][j][e] = 0.0f;

    // Per-thread fragment base offsets (bytes within tile), derived from the
    // PTX mma.m16n8k16 fragment spec:
    //   A reg0 = A[m = gid][k = tig*2, tig*2+1]   (+8 rows for reg1, +8 k for reg2/3)
    //   B reg0 = B[n = gid][k = tig*2, tig*2+1]   (+16B for k+8; +8 rows for n+8)
    const uint32_t a_base0 = (uint32_t)((wm0 + gid) * ROWB + tig * 4);
    const uint32_t b_base0 = (uint32_t)((wn0 + gid) * ROWB + tig * 4);

    for (int kc = 0; kc < NCHUNK; ++kc) {
        cp_wait1();        // chunk kc has landed (uniform: every iter commits one group)
        __syncthreads();   // everyone sees it; everyone done with chunk kc-1's stage

        {   // refill stage (kc-1)%STAGES with chunk kc+STAGES-1 (empty group at tail)
            const int kn = kc + STAGES - 1;
            if (kn < NCHUNK)
                load_chunk(sb + OFF_A + (kn % STAGES) * STAGE_BYTES, Ag, Bg, kn * KC, tid);
            cp_commit();
        }

        const uint32_t stA = sb + OFF_A + (kc % STAGES) * STAGE_BYTES;
        const uint32_t stB = stA + A_BYTES;
#pragma unroll
        for (int ks = 0; ks < 4; ++ks) {
            // ---- A fragments: 4 m-subtiles of 16 rows, K=16 slice ----
            uint32_t a[4][4];
#pragma unroll
            for (int g = 0; g < 4; ++g) {
                const uint32_t ab = stA + a_base0 + (uint32_t)(g * 16 * ROWB + ks * 32);
                a[g][0] = lds32(ab);                 // (m: gid,   k: lo8)
                a[g][1] = lds32(ab + 8 * ROWB);      // (m: gid+8, k: lo8)
                a[g][2] = lds32(ab + 16);            // (m: gid,   k: hi8)
                a[g][3] = lds32(ab + 8 * ROWB + 16); // (m: gid+8, k: hi8)
            }
            // ---- B fragments + MMAs: 4 n-subtiles of 16 cols ----
#pragma unroll
            for (int h = 0; h < 4; ++h) {
                const uint32_t bb = stB + b_base0 + (uint32_t)(h * 16 * ROWB + ks * 32);
                uint32_t blo[2], bhi[2];
                blo[0] = lds32(bb);                  // (n: gid,   k: lo8)
                blo[1] = lds32(bb + 16);             // (n: gid,   k: hi8)
                bhi[0] = lds32(bb + 8 * ROWB);       // (n: gid+8, k: lo8)
                bhi[1] = lds32(bb + 8 * ROWB + 16);  // (n: gid+8, k: hi8)
#pragma unroll
                for (int g = 0; g < 4; ++g) {
                    mma16816(acc[g][2 * h + 0], a[g], blo);  // n cols h*16 + 0..7
                    mma16816(acc[g][2 * h + 1], a[g], bhi);  // n cols h*16 + 8..15
                }
            }
        }
    }

    // epilogue: per mma, c0,c1 at (row = gid, col = tig*2..+1), c2,c3 at row+8
    const float* bsm = (const float*)(smem + OFF_BIAS);
#pragma unroll
    for (int g = 0; g < 4; ++g) {
        const int row = m0 + wm0 + g * 16 + gid;
#pragma unroll
        for (int j = 0; j < 8; ++j) {
            const int bcol = wn0 + j * 8 + tig * 2;
            const float b0 = bsm[bcol], b1 = bsm[bcol + 1];
            float* op = out + (size_t)row * NDIM + n0 + bcol;
            float2 v0 = {acc[g][j][0] + b0, acc[g][j][1] + b1};
            float2 v1 = {acc[g][j][2] + b0, acc[g][j][3] + b1};
            *reinterpret_cast<float2*>(op) = v0;
            *reinterpret_cast<float2*>(op + 8 * NDIM) = v1;
        }
    }
}

// ---------------- launch ----------------
extern "C" void kernel_launch(void* const* d_in, const int* in_sizes, int n_in,
                              void* d_out, int out_size) {
    const float* x    = (const float*)d_in[0];
    const int*   wq   = (const int*)d_in[1];    // int8 promoted to int32 on the wire
    const float* sw   = (const float*)d_in[2];
    const float* bias = (const float*)d_in[3];
    float*       out  = (float*)d_out;

    conv_x_kernel<<<(MDIM * KDIM / 4) / THREADS, THREADS>>>((const float4*)x);
    conv_w_kernel<<<((size_t)NDIM * KDIM / 4) / THREADS, THREADS>>>((const int4*)wq, sw);

    cudaFuncSetAttribute(gemm_kernel, cudaFuncAttributeMaxDynamicSharedMemorySize, SMEM_TOTAL);
    gemm_kernel<<<(MDIM / MT) * (NDIM / NT), THREADS, SMEM_TOTAL>>>(bias, out);
}

// round 7
// speedup vs baseline: 1.2743x; 1.2743x over previous
#include <cuda_runtime.h>
#include <cuda_fp16.h>
#include <cstdint>

// Problem sizes (fixed)
#define MDIM 2048
#define NDIM 4096
#define KDIM 4096
// Tiling
#define MT 128        // CTA tile M
#define NT 128        // CTA tile N
#define KC 64         // K-chunk (halves) = 128B per smem row
#define NCHUNK (KDIM / KC)   // 64
#define STAGES 3
#define THREADS 256

// Scratch (allocation-free rule: __device__ globals)
__device__ __half g_xh[(size_t)MDIM * KDIM];  // 16 MB
__device__ __half g_wh[(size_t)NDIM * KDIM];  // 32 MB

// ---------------- helpers ----------------
__device__ __forceinline__ uint32_t smem_u32(const void* p) {
    uint32_t a;
    asm("{ .reg .u64 t; cvta.to.shared.u64 t, %1; cvt.u32.u64 %0, t; }" : "=r"(a) : "l"(p));
    return a;
}
// SW128: XOR 16B-chunk index (bits 4-6) with row%8 (bits 7-9)  [proven in R4]
#define SWZ(o) ((o) ^ (((o) >> 3) & 0x70))

__device__ __forceinline__ void cp_async16(uint32_t dst, const void* src) {
    asm volatile("cp.async.cg.shared.global [%0], [%1], 16;" :: "r"(dst), "l"(src));
}
__device__ __forceinline__ void cp_commit() { asm volatile("cp.async.commit_group;"); }
__device__ __forceinline__ void cp_wait1()  { asm volatile("cp.async.wait_group 1;" ::: "memory"); }

__device__ __forceinline__ void ldsm_x4(uint32_t* r, uint32_t addr) {
    asm volatile("ldmatrix.sync.aligned.m8n8.x4.shared.b16 {%0,%1,%2,%3}, [%4];"
                 : "=r"(r[0]), "=r"(r[1]), "=r"(r[2]), "=r"(r[3]) : "r"(addr));
}
__device__ __forceinline__ void mma16816(float* d, const uint32_t* a, const uint32_t* b) {
    asm volatile(
        "mma.sync.aligned.m16n8k16.row.col.f32.f16.f16.f32 "
        "{%0,%1,%2,%3}, {%4,%5,%6,%7}, {%8,%9}, {%0,%1,%2,%3};"
        : "+f"(d[0]), "+f"(d[1]), "+f"(d[2]), "+f"(d[3])
        : "r"(a[0]), "r"(a[1]), "r"(a[2]), "r"(a[3]), "r"(b[0]), "r"(b[1]));
}

// ---------------- SMEM layout (per CTA) ----------------
#define OFF_BIAS 0                                 // 128 floats
#define OFF_A 1024
#define A_BYTES (MT * 128)                         // 16384
#define B_BYTES (NT * 128)                         // 16384
#define STAGE_BYTES (A_BYTES + B_BYTES)            // 32768
#define SMEM_TOTAL (OFF_A + STAGES * STAGE_BYTES)  // 99328 -> 2 CTAs/SM

// ---------------- conversion kernels ----------------
__global__ void conv_x_kernel(const float4* __restrict__ x) {
    int i = blockIdx.x * blockDim.x + threadIdx.x;  // MDIM*KDIM/4 threads
    float4 v = x[i];
    __half2 h0 = __floats2half2_rn(v.x, v.y);
    __half2 h1 = __floats2half2_rn(v.z, v.w);
    uint2 r;
    r.x = *reinterpret_cast<uint32_t*>(&h0);
    r.y = *reinterpret_cast<uint32_t*>(&h1);
    reinterpret_cast<uint2*>(g_xh)[i] = r;
}

// w_q arrives as int32 on the wire (harness promotes int8). 4 weights/thread.
__global__ void conv_w_kernel(const int4* __restrict__ wq, const float* __restrict__ sw) {
    int i = blockIdx.x * blockDim.x + threadIdx.x;  // NDIM*KDIM/4 threads
    int4 w = wq[i];
    int idx4 = i << 2;
    int o = idx4 >> 12;          // w_q layout (o, g, k): o*4096 + g*128 + k
    int g = (idx4 >> 7) & 31;
    float s = __ldg(&sw[(g << 12) + o]);  // s_w layout (g, o)
    __half2 h0 = __floats2half2_rn((float)w.x * s, (float)w.y * s);
    __half2 h1 = __floats2half2_rn((float)w.z * s, (float)w.w * s);
    uint2 r;
    r.x = *reinterpret_cast<uint32_t*>(&h0);
    r.y = *reinterpret_cast<uint32_t*>(&h1);
    reinterpret_cast<uint2*>(g_wh)[i] = r;
}

// ---------------- GEMM ----------------
__device__ __forceinline__ void load_chunk(uint32_t stage_base,
                                           const __half* Ag, const __half* Bg,
                                           int k0, int tid) {
    const uint32_t aB = stage_base;
    const uint32_t bB = stage_base + A_BYTES;
    // A: 128 rows x 8 x 16B = 1024 units -> 4 per thread
#pragma unroll
    for (int i = 0; i < 4; ++i) {
        int u = tid + i * THREADS;
        int row = u >> 3, c = u & 7;
        cp_async16(aB + SWZ(row * 128 + c * 16), Ag + (size_t)row * KDIM + k0 + c * 8);
    }
    // B: 128 rows -> 1024 units -> 4 per thread
#pragma unroll
    for (int i = 0; i < 4; ++i) {
        int u = tid + i * THREADS;
        int row = u >> 3, c = u & 7;
        cp_async16(bB + SWZ(row * 128 + c * 16), Bg + (size_t)row * KDIM + k0 + c * 8);
    }
}

__global__ void __launch_bounds__(THREADS, 2)
gemm_kernel(const float* __restrict__ bias, float* __restrict__ out) {
    extern __shared__ __align__(128) char smem[];
    const uint32_t sb = smem_u32(smem);
    const int tid = threadIdx.x;
    const int wid = tid >> 5;
    const int lane = tid & 31;
    const int gid = lane >> 2;   // groupID (0..7)
    const int tig = lane & 3;    // thread-in-group

    // bm fast-varying so consecutive CTAs share the B tile in L2
    const int bm = blockIdx.x & 15;   // 16 m-tiles
    const int bn = blockIdx.x >> 4;   // 32 n-tiles
    const int m0 = bm * MT;
    const int n0 = bn * NT;

    // warp tile: 64x32.  wm in {0,1}, wn in {0..3}
    const int wm0 = (wid & 1) * 64;
    const int wn0 = (wid >> 1) * 32;

    if (tid < NT) ((float*)(smem + OFF_BIAS))[tid] = bias[n0 + tid];

    const __half* Ag = g_xh + (size_t)m0 * KDIM;
    const __half* Bg = g_wh + (size_t)n0 * KDIM;

    // prologue: stages 0,1 in flight
#pragma unroll
    for (int s = 0; s < STAGES - 1; ++s) {
        load_chunk(sb + OFF_A + s * STAGE_BYTES, Ag, Bg, s * KC, tid);
        cp_commit();
    }

    float acc[4][4][4];
#pragma unroll
    for (int g = 0; g < 4; ++g)
#pragma unroll
        for (int j = 0; j < 4; ++j)
#pragma unroll
            for (int e = 0; e < 4; ++e) acc[g][j][e] = 0.0f;

    // ldmatrix lane addressing (within-tile), validated in R4:
    // A x4 -> regs (m0-7,klo),(m8-15,klo),(m0-7,khi),(m8-15,khi)
    const int a_row = wm0 + (lane & 7) + ((lane >> 3) & 1) * 8;  // + g*16
    const int a_kbo = ((lane >> 4) & 1) * 16;                    // + ks*32
    // B x4 -> regs (n0-7,klo),(n0-7,khi),(n8-15,klo),(n8-15,khi)
    const int b_row = wn0 + (lane & 7) + ((lane >> 4) & 1) * 8;  // + h*16
    const int b_kbo = ((lane >> 3) & 1) * 16;                    // + ks*32

    for (int kc = 0; kc < NCHUNK; ++kc) {
        cp_wait1();        // chunk kc has landed (uniform: one commit per iter)
        __syncthreads();   // visibility + done with the stage being refilled

        {   // refill with chunk kc+STAGES-1 (empty commit at tail keeps count uniform)
            const int kn = kc + STAGES - 1;
            if (kn < NCHUNK)
                load_chunk(sb + OFF_A + (kn % STAGES) * STAGE_BYTES, Ag, Bg, kn * KC, tid);
            cp_commit();
        }

        const uint32_t stA = sb + OFF_A + (kc % STAGES) * STAGE_BYTES;
        const uint32_t stB = stA + A_BYTES;
#pragma unroll
        for (int ks = 0; ks < 4; ++ks) {
            uint32_t a[4][4], b[2][4];
#pragma unroll
            for (int g = 0; g < 4; ++g)
                ldsm_x4(a[g], stA + SWZ((a_row + g * 16) * 128 + ks * 32 + a_kbo));
#pragma unroll
            for (int h = 0; h < 2; ++h)
                ldsm_x4(b[h], stB + SWZ((b_row + h * 16) * 128 + ks * 32 + b_kbo));
#pragma unroll
            for (int g = 0; g < 4; ++g)
#pragma unroll
                for (int h = 0; h < 2; ++h) {
                    mma16816(acc[g][2 * h + 0], a[g], &b[h][0]);  // n cols h*16+0..7
                    mma16816(acc[g][2 * h + 1], a[g], &b[h][2]);  // n cols h*16+8..15
                }
        }
    }

    // epilogue: per mma, c0,c1 at (row=gid, col=tig*2..+1), c2,c3 at row+8
    const float* bsm = (const float*)(smem + OFF_BIAS);
#pragma unroll
    for (int g = 0; g < 4; ++g) {
        const int row = m0 + wm0 + g * 16 + gid;
#pragma unroll
        for (int j = 0; j < 4; ++j) {
            const int bcol = wn0 + j * 8 + tig * 2;
            const float b0 = bsm[bcol], b1 = bsm[bcol + 1];
            float* op = out + (size_t)row * NDIM + n0 + bcol;
            float2 v0 = {acc[g][j][0] + b0, acc[g][j][1] + b1};
            float2 v1 = {acc[g][j][2] + b0, acc[g][j][3] + b1};
            *reinterpret_cast<float2*>(op) = v0;
            *reinterpret_cast<float2*>(op + 8 * NDIM) = v1;
        }
    }
}

// ---------------- launch ----------------
extern "C" void kernel_launch(void* const* d_in, const int* in_sizes, int n_in,
                              void* d_out, int out_size) {
    const float* x    = (const float*)d_in[0];
    const int*   wq   = (const int*)d_in[1];    // int8 promoted to int32 on the wire
    const float* sw   = (const float*)d_in[2];
    const float* bias = (const float*)d_in[3];
    float*       out  = (float*)d_out;

    conv_x_kernel<<<(MDIM * KDIM / 4) / THREADS, THREADS>>>((const float4*)x);
    conv_w_kernel<<<((size_t)NDIM * KDIM / 4) / THREADS, THREADS>>>((const int4*)wq, sw);

    cudaFuncSetAttribute(gemm_kernel, cudaFuncAttributeMaxDynamicSharedMemorySize, SMEM_TOTAL);
    gemm_kernel<<<(MDIM / MT) * (NDIM / NT), THREADS, SMEM_TOTAL>>>(bias, out);
}

// round 8
// speedup vs baseline: 1.3144x; 1.0315x over previous
#include <cuda_runtime.h>
#include <cuda_fp16.h>
#include <cstdint>

// Problem sizes (fixed)
#define MDIM 2048
#define NDIM 4096
#define KDIM 4096
// Tiling
#define MT 128        // CTA tile M
#define NT 128        // CTA tile N
#define KC 64         // K-chunk (halves) = 128B per smem row
#define NCHUNK (KDIM / KC)   // 64
#define STAGES 3
#define THREADS 256

// Scratch (allocation-free rule: __device__ globals)
__device__ __half g_xh[(size_t)MDIM * KDIM];  // 16 MB
__device__ __half g_wh[(size_t)NDIM * KDIM];  // 32 MB

// ---------------- helpers ----------------
__device__ __forceinline__ uint32_t smem_u32(const void* p) {
    uint32_t a;
    asm("{ .reg .u64 t; cvta.to.shared.u64 t, %1; cvt.u32.u64 %0, t; }" : "=r"(a) : "l"(p));
    return a;
}
// SW128: XOR 16B-chunk index (bits 4-6) with row%8 (bits 7-9)  [proven]
#define SWZ(o) ((o) ^ (((o) >> 3) & 0x70))

__device__ __forceinline__ void cp_async16(uint32_t dst, const void* src) {
    asm volatile("cp.async.cg.shared.global [%0], [%1], 16;" :: "r"(dst), "l"(src));
}
__device__ __forceinline__ void cp_commit() { asm volatile("cp.async.commit_group;"); }
__device__ __forceinline__ void cp_wait1()  { asm volatile("cp.async.wait_group 1;" ::: "memory"); }

__device__ __forceinline__ void ldsm_x4(uint32_t* r, uint32_t addr) {
    asm volatile("ldmatrix.sync.aligned.m8n8.x4.shared.b16 {%0,%1,%2,%3}, [%4];"
                 : "=r"(r[0]), "=r"(r[1]), "=r"(r[2]), "=r"(r[3]) : "r"(addr));
}
__device__ __forceinline__ void mma16816(float* d, const uint32_t* a, const uint32_t* b) {
    asm volatile(
        "mma.sync.aligned.m16n8k16.row.col.f32.f16.f16.f32 "
        "{%0,%1,%2,%3}, {%4,%5,%6,%7}, {%8,%9}, {%0,%1,%2,%3};"
        : "+f"(d[0]), "+f"(d[1]), "+f"(d[2]), "+f"(d[3])
        : "r"(a[0]), "r"(a[1]), "r"(a[2]), "r"(a[3]), "r"(b[0]), "r"(b[1]));
}

// ---------------- SMEM layout (per CTA) ----------------
#define OFF_BIAS 0                                 // 128 floats
#define OFF_A 1024
#define A_BYTES (MT * 128)                         // 16384
#define B_BYTES (NT * 128)                         // 16384
#define STAGE_BYTES (A_BYTES + B_BYTES)            // 32768
#define SMEM_TOTAL (OFF_A + STAGES * STAGE_BYTES)  // 99328 -> 2 CTAs/SM

// ---------------- fused conversion kernel ----------------
// Blocks [0, XBLK): fp32 x -> fp16 (4 float4 units per thread, MLP=4)
// Blocks [XBLK, XBLK+WBLK): int32 w * scale -> fp16 (4 int4 units per thread)
#define XUNITS (MDIM * KDIM / 4)          // 2,097,152 float4 units
#define WUNITS (NDIM * KDIM / 4)          // 4,194,304 int4 units
#define XBLK (XUNITS / (THREADS * 4))     // 2048
#define WBLK (WUNITS / (THREADS * 4))     // 4096

__global__ void conv_fused_kernel(const float4* __restrict__ x,
                                  const int4* __restrict__ wq,
                                  const float* __restrict__ sw) {
    const int tid = threadIdx.x;
    if (blockIdx.x < XBLK) {
        const int base = blockIdx.x * (THREADS * 4) + tid;
        float4 v[4];
#pragma unroll
        for (int j = 0; j < 4; ++j) v[j] = x[base + j * THREADS];
#pragma unroll
        for (int j = 0; j < 4; ++j) {
            __half2 h0 = __floats2half2_rn(v[j].x, v[j].y);
            __half2 h1 = __floats2half2_rn(v[j].z, v[j].w);
            uint2 r;
            r.x = *reinterpret_cast<uint32_t*>(&h0);
            r.y = *reinterpret_cast<uint32_t*>(&h1);
            reinterpret_cast<uint2*>(g_xh)[base + j * THREADS] = r;
        }
    } else {
        const int base = (blockIdx.x - XBLK) * (THREADS * 4) + tid;
        int4 w[4];
#pragma unroll
        for (int j = 0; j < 4; ++j) w[j] = wq[base + j * THREADS];
#pragma unroll
        for (int j = 0; j < 4; ++j) {
            const int i = base + j * THREADS;
            const int idx4 = i << 2;
            const int o = idx4 >> 12;          // w_q (o,g,k): o*4096 + g*128 + k
            const int g = (idx4 >> 7) & 31;
            const float s = __ldg(&sw[(g << 12) + o]);  // s_w (g,o)
            __half2 h0 = __floats2half2_rn((float)w[j].x * s, (float)w[j].y * s);
            __half2 h1 = __floats2half2_rn((float)w[j].z * s, (float)w[j].w * s);
            uint2 r;
            r.x = *reinterpret_cast<uint32_t*>(&h0);
            r.y = *reinterpret_cast<uint32_t*>(&h1);
            reinterpret_cast<uint2*>(g_wh)[i] = r;
        }
    }
}

// ---------------- GEMM (unchanged from R7 — proven) ----------------
__device__ __forceinline__ void load_chunk(uint32_t stage_base,
                                           const __half* Ag, const __half* Bg,
                                           int k0, int tid) {
    const uint32_t aB = stage_base;
    const uint32_t bB = stage_base + A_BYTES;
#pragma unroll
    for (int i = 0; i < 4; ++i) {
        int u = tid + i * THREADS;
        int row = u >> 3, c = u & 7;
        cp_async16(aB + SWZ(row * 128 + c * 16), Ag + (size_t)row * KDIM + k0 + c * 8);
    }
#pragma unroll
    for (int i = 0; i < 4; ++i) {
        int u = tid + i * THREADS;
        int row = u >> 3, c = u & 7;
        cp_async16(bB + SWZ(row * 128 + c * 16), Bg + (size_t)row * KDIM + k0 + c * 8);
    }
}

__global__ void __launch_bounds__(THREADS, 2)
gemm_kernel(const float* __restrict__ bias, float* __restrict__ out) {
    extern __shared__ __align__(128) char smem[];
    const uint32_t sb = smem_u32(smem);
    const int tid = threadIdx.x;
    const int wid = tid >> 5;
    const int lane = tid & 31;
    const int gid = lane >> 2;   // groupID (0..7)
    const int tig = lane & 3;    // thread-in-group

    // bm fast-varying so consecutive CTAs share the B tile in L2
    const int bm = blockIdx.x & 15;   // 16 m-tiles
    const int bn = blockIdx.x >> 4;   // 32 n-tiles
    const int m0 = bm * MT;
    const int n0 = bn * NT;

    // warp tile: 64x32
    const int wm0 = (wid & 1) * 64;
    const int wn0 = (wid >> 1) * 32;

    if (tid < NT) ((float*)(smem + OFF_BIAS))[tid] = bias[n0 + tid];

    const __half* Ag = g_xh + (size_t)m0 * KDIM;
    const __half* Bg = g_wh + (size_t)n0 * KDIM;

#pragma unroll
    for (int s = 0; s < STAGES - 1; ++s) {
        load_chunk(sb + OFF_A + s * STAGE_BYTES, Ag, Bg, s * KC, tid);
        cp_commit();
    }

    float acc[4][4][4];
#pragma unroll
    for (int g = 0; g < 4; ++g)
#pragma unroll
        for (int j = 0; j < 4; ++j)
#pragma unroll
            for (int e = 0; e < 4; ++e) acc[g][j][e] = 0.0f;

    // ldmatrix lane addressing (validated)
    const int a_row = wm0 + (lane & 7) + ((lane >> 3) & 1) * 8;  // + g*16
    const int a_kbo = ((lane >> 4) & 1) * 16;                    // + ks*32
    const int b_row = wn0 + (lane & 7) + ((lane >> 4) & 1) * 8;  // + h*16
    const int b_kbo = ((lane >> 3) & 1) * 16;                    // + ks*32

    for (int kc = 0; kc < NCHUNK; ++kc) {
        cp_wait1();
        __syncthreads();

        {
            const int kn = kc + STAGES - 1;
            if (kn < NCHUNK)
                load_chunk(sb + OFF_A + (kn % STAGES) * STAGE_BYTES, Ag, Bg, kn * KC, tid);
            cp_commit();
        }

        const uint32_t stA = sb + OFF_A + (kc % STAGES) * STAGE_BYTES;
        const uint32_t stB = stA + A_BYTES;
#pragma unroll
        for (int ks = 0; ks < 4; ++ks) {
            uint32_t a[4][4], b[2][4];
#pragma unroll
            for (int g = 0; g < 4; ++g)
                ldsm_x4(a[g], stA + SWZ((a_row + g * 16) * 128 + ks * 32 + a_kbo));
#pragma unroll
            for (int h = 0; h < 2; ++h)
                ldsm_x4(b[h], stB + SWZ((b_row + h * 16) * 128 + ks * 32 + b_kbo));
#pragma unroll
            for (int g = 0; g < 4; ++g)
#pragma unroll
                for (int h = 0; h < 2; ++h) {
                    mma16816(acc[g][2 * h + 0], a[g], &b[h][0]);
                    mma16816(acc[g][2 * h + 1], a[g], &b[h][2]);
                }
        }
    }

    // epilogue
    const float* bsm = (const float*)(smem + OFF_BIAS);
#pragma unroll
    for (int g = 0; g < 4; ++g) {
        const int row = m0 + wm0 + g * 16 + gid;
#pragma unroll
        for (int j = 0; j < 4; ++j) {
            const int bcol = wn0 + j * 8 + tig * 2;
            const float b0 = bsm[bcol], b1 = bsm[bcol + 1];
            float* op = out + (size_t)row * NDIM + n0 + bcol;
            float2 v0 = {acc[g][j][0] + b0, acc[g][j][1] + b1};
            float2 v1 = {acc[g][j][2] + b0, acc[g][j][3] + b1};
            *reinterpret_cast<float2*>(op) = v0;
            *reinterpret_cast<float2*>(op + 8 * NDIM) = v1;
        }
    }
}

// ---------------- launch ----------------
extern "C" void kernel_launch(void* const* d_in, const int* in_sizes, int n_in,
                              void* d_out, int out_size) {
    const float* x    = (const float*)d_in[0];
    const int*   wq   = (const int*)d_in[1];    // int8 promoted to int32 on the wire
    const float* sw   = (const float*)d_in[2];
    const float* bias = (const float*)d_in[3];
    float*       out  = (float*)d_out;

    conv_fused_kernel<<<XBLK + WBLK, THREADS>>>((const float4*)x, (const int4*)wq, sw);

    cudaFuncSetAttribute(gemm_kernel, cudaFuncAttributeMaxDynamicSharedMemorySize, SMEM_TOTAL);
    gemm_kernel<<<(MDIM / MT) * (NDIM / NT), THREADS, SMEM_TOTAL>>>(bias, out);
}